// round 1
// baseline (speedup 1.0000x reference)
#include <cuda_runtime.h>
#include <cuda_bf16.h>
#include <math.h>

// Problem constants (fixed by setup_inputs)
#define BB 8
#define HH 37
#define WW 37
#define NN (HH * WW)          // 1369
#define CC 1024
#define MM (BB * NN)          // 10952
#define NHEADS 8
#define HD 128
#define NPTS 8

// Scratch (static device allocations are allowed)
__device__ float g_q[MM * CC];
__device__ float g_k[MM * CC];
__device__ float g_off[MM * (NHEADS * NPTS * 2)];
__device__ float g_attn[MM * CC];

// ---------------------------------------------------------------------------
// Classic 128x128x8 fp32 SGEMM with bias: C[M,N] = A[M,K] @ B[K,N] + bias[N]
// A row-major lda=K, B row-major leading dim ldb (>= N), C row-major ld=N.
// 256 threads, 8x8 per-thread microtile.
// ---------------------------------------------------------------------------
__global__ __launch_bounds__(256, 2)
void sgemm_bias(const float* __restrict__ A, const float* __restrict__ B,
                const float* __restrict__ bias, float* __restrict__ Cm,
                int M, int N, int K, int ldb) {
    __shared__ float As[8][128];
    __shared__ float Bs[8][128];

    const int tid = threadIdx.x;
    const int row0 = blockIdx.y * 128;
    const int col0 = blockIdx.x * 128;

    const int tr = (tid >> 4) * 8;        // 0..120
    const int tc = (tid & 15) * 8;        // 0..120

    // A loader: 128 rows x 8 k, one float4 per thread
    const int arow = tid >> 1;
    const int acol = (tid & 1) * 4;
    // B loader: 8 rows x 128 cols, one float4 per thread
    const int brl = tid >> 5;
    const int bcl = (tid & 31) * 4;

    float acc[8][8];
#pragma unroll
    for (int i = 0; i < 8; i++)
#pragma unroll
        for (int j = 0; j < 8; j++) acc[i][j] = 0.0f;

    for (int k0 = 0; k0 < K; k0 += 8) {
        float4 av = make_float4(0.f, 0.f, 0.f, 0.f);
        int ga = row0 + arow;
        if (ga < M)
            av = *reinterpret_cast<const float4*>(A + (size_t)ga * K + k0 + acol);
        // transpose into As[k][m]
        As[acol + 0][arow] = av.x;
        As[acol + 1][arow] = av.y;
        As[acol + 2][arow] = av.z;
        As[acol + 3][arow] = av.w;

        float4 bv = *reinterpret_cast<const float4*>(B + (size_t)(k0 + brl) * ldb + col0 + bcl);
        *reinterpret_cast<float4*>(&Bs[brl][bcl]) = bv;

        __syncthreads();

#pragma unroll
        for (int kk = 0; kk < 8; kk++) {
            float4 a0 = *reinterpret_cast<const float4*>(&As[kk][tr]);
            float4 a1 = *reinterpret_cast<const float4*>(&As[kk][tr + 4]);
            float4 b0 = *reinterpret_cast<const float4*>(&Bs[kk][tc]);
            float4 b1 = *reinterpret_cast<const float4*>(&Bs[kk][tc + 4]);
            float ar[8] = {a0.x, a0.y, a0.z, a0.w, a1.x, a1.y, a1.z, a1.w};
            float br[8] = {b0.x, b0.y, b0.z, b0.w, b1.x, b1.y, b1.z, b1.w};
#pragma unroll
            for (int i = 0; i < 8; i++)
#pragma unroll
                for (int j = 0; j < 8; j++) acc[i][j] += ar[i] * br[j];
        }
        __syncthreads();
    }

    float bvreg[8];
#pragma unroll
    for (int j = 0; j < 8; j++) bvreg[j] = bias[col0 + tc + j];

#pragma unroll
    for (int i = 0; i < 8; i++) {
        int r = row0 + tr + i;
        if (r < M) {
            float* cp = Cm + (size_t)r * N + col0 + tc;
            float4 o0, o1;
            o0.x = acc[i][0] + bvreg[0]; o0.y = acc[i][1] + bvreg[1];
            o0.z = acc[i][2] + bvreg[2]; o0.w = acc[i][3] + bvreg[3];
            o1.x = acc[i][4] + bvreg[4]; o1.y = acc[i][5] + bvreg[5];
            o1.z = acc[i][6] + bvreg[6]; o1.w = acc[i][7] + bvreg[7];
            *reinterpret_cast<float4*>(cp) = o0;
            *reinterpret_cast<float4*>(cp + 4) = o1;
        }
    }
}

// ---------------------------------------------------------------------------
// Sampling + attention. One warp per (b, n, head).
// Each lane owns 4 of the 128 channels. The 8 sampled vectors live in regs.
// Replicates the reference's channel swap: locs[...,0] -> x, locs[...,1] -> y.
// ---------------------------------------------------------------------------
__global__ __launch_bounds__(256)
void sample_attn_kernel(const float* __restrict__ q, const float* __restrict__ k,
                        const float* __restrict__ off, float* __restrict__ out) {
    const int gwarp = (blockIdx.x * blockDim.x + threadIdx.x) >> 5;
    const int lane = threadIdx.x & 31;
    if (gwarp >= MM * NHEADS) return;

    const int h = gwarp & (NHEADS - 1);
    const int m = gwarp >> 3;           // b*NN + n
    const int n = m % NN;
    const int b = m / NN;

    const int ch = h * HD + lane * 4;
    float4 qv = *reinterpret_cast<const float4*>(q + (size_t)m * CC + ch);

    const int iy_n = n / WW;
    const int ix_n = n % WW;
    const float cy = -1.0f + 2.0f * (float)iy_n / (float)(HH - 1);
    const float cx = -1.0f + 2.0f * (float)ix_n / (float)(WW - 1);

    const float* offp = off + (size_t)m * (NHEADS * NPTS * 2) + h * (NPTS * 2);
    const float* kb = k + (size_t)b * NN * CC;

    float sk[NPTS][4];
    float score[NPTS];
    const float scale = 0.08838834764831845f;  // 128^-0.5

#pragma unroll
    for (int p = 0; p < NPTS; p++) {
        float l0 = cy + offp[2 * p + 0];   // channel 0 -> x index (reference swap)
        float l1 = cx + offp[2 * p + 1];   // channel 1 -> y index
        float ix = (l0 + 1.0f) * 0.5f * (float)(WW - 1);
        float iy = (l1 + 1.0f) * 0.5f * (float)(HH - 1);
        ix = fminf(fmaxf(ix, 0.0f), (float)(WW - 1));
        iy = fminf(fmaxf(iy, 0.0f), (float)(HH - 1));
        float x0f = floorf(ix), y0f = floorf(iy);
        float wx = ix - x0f, wy = iy - y0f;
        int x0 = (int)x0f, y0 = (int)y0f;
        int x1 = min(x0 + 1, WW - 1);
        int y1 = min(y0 + 1, HH - 1);

        const float4 g00 = *reinterpret_cast<const float4*>(kb + (size_t)(y0 * WW + x0) * CC + ch);
        const float4 g01 = *reinterpret_cast<const float4*>(kb + (size_t)(y0 * WW + x1) * CC + ch);
        const float4 g10 = *reinterpret_cast<const float4*>(kb + (size_t)(y1 * WW + x0) * CC + ch);
        const float4 g11 = *reinterpret_cast<const float4*>(kb + (size_t)(y1 * WW + x1) * CC + ch);

        float w00 = (1.0f - wy) * (1.0f - wx);
        float w01 = (1.0f - wy) * wx;
        float w10 = wy * (1.0f - wx);
        float w11 = wy * wx;

        sk[p][0] = g00.x * w00 + g01.x * w01 + g10.x * w10 + g11.x * w11;
        sk[p][1] = g00.y * w00 + g01.y * w01 + g10.y * w10 + g11.y * w11;
        sk[p][2] = g00.z * w00 + g01.z * w01 + g10.z * w10 + g11.z * w11;
        sk[p][3] = g00.w * w00 + g01.w * w01 + g10.w * w10 + g11.w * w11;

        float s = qv.x * sk[p][0] + qv.y * sk[p][1] + qv.z * sk[p][2] + qv.w * sk[p][3];
#pragma unroll
        for (int d = 16; d > 0; d >>= 1)
            s += __shfl_xor_sync(0xFFFFFFFFu, s, d);
        score[p] = s * scale;
    }

    // softmax over the 8 points (every lane has identical scores)
    float mx = score[0];
#pragma unroll
    for (int p = 1; p < NPTS; p++) mx = fmaxf(mx, score[p]);
    float denom = 0.0f;
    float e[NPTS];
#pragma unroll
    for (int p = 0; p < NPTS; p++) { e[p] = expf(score[p] - mx); denom += e[p]; }
    float inv = 1.0f / denom;

    float4 acc = make_float4(0.f, 0.f, 0.f, 0.f);
#pragma unroll
    for (int p = 0; p < NPTS; p++) {
        float a = e[p] * inv;
        acc.x += a * sk[p][0];
        acc.y += a * sk[p][1];
        acc.z += a * sk[p][2];
        acc.w += a * sk[p][3];
    }
    *reinterpret_cast<float4*>(out + (size_t)m * CC + ch) = acc;
}

// ---------------------------------------------------------------------------
extern "C" void kernel_launch(void* const* d_in, const int* in_sizes, int n_in,
                              void* d_out, int out_size) {
    const float* query = (const float*)d_in[0];
    const float* ref   = (const float*)d_in[1];
    const float* Wq    = (const float*)d_in[2];
    const float* bq    = (const float*)d_in[3];
    const float* Wkv   = (const float*)d_in[4];
    const float* bkv   = (const float*)d_in[5];
    const float* Woff  = (const float*)d_in[6];
    const float* boff  = (const float*)d_in[7];
    const float* Wout  = (const float*)d_in[8];
    const float* bout  = (const float*)d_in[9];
    float* outp = (float*)d_out;

    float *qb, *kb, *offb, *attnb;
    cudaGetSymbolAddress((void**)&qb, g_q);
    cudaGetSymbolAddress((void**)&kb, g_k);
    cudaGetSymbolAddress((void**)&offb, g_off);
    cudaGetSymbolAddress((void**)&attnb, g_attn);

    const int mtiles = (MM + 127) / 128;  // 86

    // q = query @ Wq + bq
    {
        dim3 grid(CC / 128, mtiles);
        sgemm_bias<<<grid, 256>>>(query, Wq, bq, qb, MM, CC, CC, CC);
    }
    // k = ref @ Wkv[:, :C] + bkv[:C]   (v half is dead code in the reference)
    {
        dim3 grid(CC / 128, mtiles);
        sgemm_bias<<<grid, 256>>>(ref, Wkv, bkv, kb, MM, CC, CC, 2 * CC);
    }
    // off = query @ Woff + boff  (N = 128)
    {
        dim3 grid(1, mtiles);
        sgemm_bias<<<grid, 256>>>(query, Woff, boff, offb, MM, NHEADS * NPTS * 2, CC,
                                  NHEADS * NPTS * 2);
    }
    // deformable sampling + softmax attention
    {
        int warps = MM * NHEADS;                  // 87616
        int blocks = (warps * 32 + 255) / 256;    // 10952
        sample_attn_kernel<<<blocks, 256>>>(qb, kb, offb, attnb);
    }
    // out = attn @ Wout + bout
    {
        dim3 grid(CC / 128, mtiles);
        sgemm_bias<<<grid, 256>>>(attnb, Wout, bout, outp, MM, CC, CC, CC);
    }
}

// round 3
// speedup vs baseline: 3.2042x; 3.2042x over previous
#include <cuda_runtime.h>
#include <cuda_bf16.h>
#include <math.h>
#include <cstdint>

// Problem constants
#define BB 8
#define HH 37
#define WW 37
#define NN (HH * WW)          // 1369
#define CC 1024
#define MM (BB * NN)          // 10952
#define NHEADS 8
#define HD 128
#define NPTS 8
#define K3 3072               // split-K: [Ah | Al | Ah] x [Bh ; Bh ; Bl]
#define NCHUNK (K3 / 64)      // 48
#define STAGES 3
#define STAGE_BYTES 32768     // A 16K + B 16K
#define SMEM_SZ (STAGES * STAGE_BYTES)

// ---------------------------------------------------------------------------
// Scratch
// ---------------------------------------------------------------------------
__device__ __nv_bfloat16 g_abig[MM * K3];
__device__ __nv_bfloat16 g_bop_q[CC * K3];
__device__ __nv_bfloat16 g_bop_k[CC * K3];
__device__ __nv_bfloat16 g_bop_o[CC * K3];
__device__ __nv_bfloat16 g_bop_f[128 * K3];
__device__ float g_q[MM * CC];
__device__ float g_k[MM * CC];
__device__ float g_offp[MM * 128];
__device__ float g_attn[MM * CC];

// ---------------------------------------------------------------------------
__device__ __forceinline__ uint32_t smem_u32(const void* p) {
    uint32_t a;
    asm("{ .reg .u64 t; cvta.to.shared.u64 t, %1; cvt.u32.u64 %0, t; }" : "=r"(a) : "l"(p));
    return a;
}
__device__ __forceinline__ void cp16(uint32_t dst, const void* src, bool valid) {
    int sz = valid ? 16 : 0;
    asm volatile("cp.async.cg.shared.global [%0], [%1], 16, %2;"
                 :: "r"(dst), "l"(src), "r"(sz) : "memory");
}
#define CP_COMMIT() asm volatile("cp.async.commit_group;" ::: "memory")
#define CP_WAIT1()  asm volatile("cp.async.wait_group 1;" ::: "memory")

__device__ __forceinline__ void ldsm4(uint32_t* r, uint32_t addr) {
    asm volatile("ldmatrix.sync.aligned.m8n8.x4.shared.b16 {%0,%1,%2,%3}, [%4];"
                 : "=r"(r[0]), "=r"(r[1]), "=r"(r[2]), "=r"(r[3]) : "r"(addr));
}
__device__ __forceinline__ void mma16816(float* c, const uint32_t* a, const uint32_t* b) {
    asm volatile(
        "mma.sync.aligned.m16n8k16.row.col.f32.bf16.bf16.f32 "
        "{%0,%1,%2,%3},{%4,%5,%6,%7},{%8,%9},{%0,%1,%2,%3};"
        : "+f"(c[0]), "+f"(c[1]), "+f"(c[2]), "+f"(c[3])
        : "r"(a[0]), "r"(a[1]), "r"(a[2]), "r"(a[3]), "r"(b[0]), "r"(b[1]));
}

// ---------------------------------------------------------------------------
// bf16 HMMA GEMM: C[M x 128-tile] = A[M,3072] x Bop[n][3072]^T + bias
// CTA 128x128, 8 warps (2 m x 4 n), warp tile 64x32. 3-stage cp.async pipeline.
// SMEM per stage: A[128 rows][64 bf16] + B[128 rows][64 bf16], XOR-swizzled.
// ---------------------------------------------------------------------------
__global__ __launch_bounds__(256)
void gemm_hmma(const __nv_bfloat16* __restrict__ A, const __nv_bfloat16* __restrict__ B,
               const float* __restrict__ bias, float* __restrict__ C, int M, int ldc) {
    extern __shared__ char smem[];
    const uint32_t sb0 = smem_u32(smem);
    const int tid = threadIdx.x, wid = tid >> 5, lane = tid & 31;
    const int m0 = blockIdx.y * 128;
    const int col0 = blockIdx.x * 128;
    const __nv_bfloat16* Bc0 = B + (size_t)col0 * K3;

    // cooperative loader indices: 1024 16B transfers per operand per stage
    auto load_stage = [&](int ck, int stage) {
        const uint32_t sa = sb0 + stage * STAGE_BYTES;
        const __nv_bfloat16* Ac = A + ck * 64;
        const __nv_bfloat16* Bc = Bc0 + ck * 64;
#pragma unroll
        for (int i = 0; i < 4; i++) {
            int id = tid + i * 256;
            int row = id >> 3, c16 = id & 7;
            int gr = m0 + row;
            bool v = gr < M;
            int grc = v ? gr : (M - 1);
            uint32_t dst = sa + row * 128 + (((uint32_t)c16 ^ (row & 7)) << 4);
            cp16(dst, Ac + (size_t)grc * K3 + c16 * 8, v);
        }
#pragma unroll
        for (int i = 0; i < 4; i++) {
            int id = tid + i * 256;
            int row = id >> 3, c16 = id & 7;
            uint32_t dst = sa + 16384 + row * 128 + (((uint32_t)c16 ^ (row & 7)) << 4);
            cp16(dst, Bc + (size_t)row * K3 + c16 * 8, true);
        }
        CP_COMMIT();
    };

    float acc[4][4][4];
#pragma unroll
    for (int mt = 0; mt < 4; mt++)
#pragma unroll
        for (int nt = 0; nt < 4; nt++)
#pragma unroll
            for (int j = 0; j < 4; j++) acc[mt][nt][j] = 0.0f;

    load_stage(0, 0);
    load_stage(1, 1);

    const int wm = (wid & 1) * 64;      // warp m offset
    const int wn = (wid >> 1) * 32;     // warp n offset

    for (int c = 0; c < NCHUNK; c++) {
        CP_WAIT1();
        __syncthreads();
        if (c + 2 < NCHUNK) load_stage(c + 2, (c + 2) % STAGES);
        else CP_COMMIT();

        const uint32_t sa = sb0 + (c % STAGES) * STAGE_BYTES;
        const uint32_t sbB = sa + 16384;

#pragma unroll
        for (int ks = 0; ks < 4; ks++) {
            uint32_t af[4][4];
#pragma unroll
            for (int mt = 0; mt < 4; mt++) {
                int row = wm + mt * 16 + (lane & 15);
                uint32_t c16 = (uint32_t)(ks * 2 + (lane >> 4)) ^ (row & 7);
                ldsm4(af[mt], sa + row * 128 + (c16 << 4));
            }
            uint32_t bf[4][2];
#pragma unroll
            for (int nt2 = 0; nt2 < 2; nt2++) {
                int group = lane >> 3;
                int nrow = wn + nt2 * 16 + (group >> 1) * 8 + (lane & 7);
                uint32_t c16 = (uint32_t)(ks * 2 + (group & 1)) ^ (nrow & 7);
                uint32_t r[4];
                ldsm4(r, sbB + nrow * 128 + (c16 << 4));
                bf[nt2 * 2][0] = r[0]; bf[nt2 * 2][1] = r[1];
                bf[nt2 * 2 + 1][0] = r[2]; bf[nt2 * 2 + 1][1] = r[3];
            }
#pragma unroll
            for (int mt = 0; mt < 4; mt++)
#pragma unroll
                for (int nt = 0; nt < 4; nt++)
                    mma16816(acc[mt][nt], af[mt], bf[nt]);
        }
        __syncthreads();
    }

    // epilogue: c0,c1 -> (row, col..col+1), c2,c3 -> (row+8, ...)
    const int lr = lane >> 2, lc = (lane & 3) * 2;
#pragma unroll
    for (int mt = 0; mt < 4; mt++) {
#pragma unroll
        for (int nt = 0; nt < 4; nt++) {
            int r0 = m0 + wm + mt * 16 + lr;
            int cb = col0 + wn + nt * 8 + lc;
            float b0 = bias[cb], b1 = bias[cb + 1];
            if (r0 < M) {
                float2 v = make_float2(acc[mt][nt][0] + b0, acc[mt][nt][1] + b1);
                *reinterpret_cast<float2*>(C + (size_t)r0 * ldc + cb) = v;
            }
            int r1 = r0 + 8;
            if (r1 < M) {
                float2 v = make_float2(acc[mt][nt][2] + b0, acc[mt][nt][3] + b1);
                *reinterpret_cast<float2*>(C + (size_t)r1 * ldc + cb) = v;
            }
        }
    }
}

// ---------------------------------------------------------------------------
// Activation conversion: fp32 [M][1024] -> bf16 [M][3072] as [hi | lo | hi]
// ---------------------------------------------------------------------------
__global__ __launch_bounds__(256)
void conv_act(const float* __restrict__ A, __nv_bfloat16* __restrict__ out) {
    size_t i = (size_t)blockIdx.x * blockDim.x + threadIdx.x;
    if (i >= (size_t)MM * 128) return;
    size_t r = i >> 7;
    int c8 = (int)(i & 127) * 8;
    const float4* p = reinterpret_cast<const float4*>(A + r * CC + c8);
    float4 v0 = p[0], v1 = p[1];
    float vv[8] = {v0.x, v0.y, v0.z, v0.w, v1.x, v1.y, v1.z, v1.w};
    __nv_bfloat16 hi[8], lo[8];
#pragma unroll
    for (int j = 0; j < 8; j++) {
        hi[j] = __float2bfloat16(vv[j]);
        lo[j] = __float2bfloat16(vv[j] - __bfloat162float(hi[j]));
    }
    __nv_bfloat16* rp = out + r * K3;
    *reinterpret_cast<uint4*>(rp + c8)        = *reinterpret_cast<uint4*>(hi);
    *reinterpret_cast<uint4*>(rp + c8 + 1024) = *reinterpret_cast<uint4*>(lo);
    *reinterpret_cast<uint4*>(rp + c8 + 2048) = *reinterpret_cast<uint4*>(hi);
}

// ---------------------------------------------------------------------------
// Weight conversion (transpose): W[1024][ldw] cols [0,nvalid) ->
// Bop[n][3072] = [hi | hi | lo]
// ---------------------------------------------------------------------------
__global__ __launch_bounds__(256)
void conv_w(const float* __restrict__ W, int ldw, int nvalid, __nv_bfloat16* __restrict__ Bop) {
    __shared__ float t[32][33];
    const int n0 = blockIdx.x * 32, k0 = blockIdx.y * 32;
    const int tx = threadIdx.x, ty = threadIdx.y;
#pragma unroll
    for (int j = ty; j < 32; j += 8) {
        int n = n0 + tx, k = k0 + j;
        t[j][tx] = (n < nvalid) ? W[(size_t)k * ldw + n] : 0.0f;
    }
    __syncthreads();
#pragma unroll
    for (int j = ty; j < 32; j += 8) {
        int n = n0 + j, k = k0 + tx;
        float v = t[tx][j];
        __nv_bfloat16 h = __float2bfloat16(v);
        __nv_bfloat16 l = __float2bfloat16(v - __bfloat162float(h));
        __nv_bfloat16* row = Bop + (size_t)n * K3;
        row[k] = h; row[k + 1024] = h; row[k + 2048] = l;
    }
}

// ---------------------------------------------------------------------------
// Sampling + attention. One warp per (b, n, head). off stride = 128.
// ---------------------------------------------------------------------------
__global__ __launch_bounds__(256)
void sample_attn_kernel(const float* __restrict__ q, const float* __restrict__ k,
                        const float* __restrict__ off, float* __restrict__ out) {
    const int gwarp = (blockIdx.x * blockDim.x + threadIdx.x) >> 5;
    const int lane = threadIdx.x & 31;
    if (gwarp >= MM * NHEADS) return;

    const int h = gwarp & (NHEADS - 1);
    const int m = gwarp >> 3;
    const int n = m % NN;
    const int b = m / NN;

    const int ch = h * HD + lane * 4;
    float4 qv = *reinterpret_cast<const float4*>(q + (size_t)m * CC + ch);

    const int iy_n = n / WW;
    const int ix_n = n % WW;
    const float cy = -1.0f + 2.0f * (float)iy_n / (float)(HH - 1);
    const float cx = -1.0f + 2.0f * (float)ix_n / (float)(WW - 1);

    const float* offp = off + (size_t)m * 128 + h * (NPTS * 2);
    const float* kb = k + (size_t)b * NN * CC;

    float sk[NPTS][4];
    float score[NPTS];
    const float scale = 0.08838834764831845f;

#pragma unroll
    for (int p = 0; p < NPTS; p++) {
        float l0 = cy + offp[2 * p + 0];
        float l1 = cx + offp[2 * p + 1];
        float ix = (l0 + 1.0f) * 0.5f * (float)(WW - 1);
        float iy = (l1 + 1.0f) * 0.5f * (float)(HH - 1);
        ix = fminf(fmaxf(ix, 0.0f), (float)(WW - 1));
        iy = fminf(fmaxf(iy, 0.0f), (float)(HH - 1));
        float x0f = floorf(ix), y0f = floorf(iy);
        float wx = ix - x0f, wy = iy - y0f;
        int x0 = (int)x0f, y0 = (int)y0f;
        int x1 = min(x0 + 1, WW - 1);
        int y1 = min(y0 + 1, HH - 1);

        const float4 g00 = *reinterpret_cast<const float4*>(kb + (size_t)(y0 * WW + x0) * CC + ch);
        const float4 g01 = *reinterpret_cast<const float4*>(kb + (size_t)(y0 * WW + x1) * CC + ch);
        const float4 g10 = *reinterpret_cast<const float4*>(kb + (size_t)(y1 * WW + x0) * CC + ch);
        const float4 g11 = *reinterpret_cast<const float4*>(kb + (size_t)(y1 * WW + x1) * CC + ch);

        float w00 = (1.0f - wy) * (1.0f - wx);
        float w01 = (1.0f - wy) * wx;
        float w10 = wy * (1.0f - wx);
        float w11 = wy * wx;

        sk[p][0] = g00.x * w00 + g01.x * w01 + g10.x * w10 + g11.x * w11;
        sk[p][1] = g00.y * w00 + g01.y * w01 + g10.y * w10 + g11.y * w11;
        sk[p][2] = g00.z * w00 + g01.z * w01 + g10.z * w10 + g11.z * w11;
        sk[p][3] = g00.w * w00 + g01.w * w01 + g10.w * w10 + g11.w * w11;

        float s = qv.x * sk[p][0] + qv.y * sk[p][1] + qv.z * sk[p][2] + qv.w * sk[p][3];
#pragma unroll
        for (int d = 16; d > 0; d >>= 1)
            s += __shfl_xor_sync(0xFFFFFFFFu, s, d);
        score[p] = s * scale;
    }

    float mx = score[0];
#pragma unroll
    for (int p = 1; p < NPTS; p++) mx = fmaxf(mx, score[p]);
    float denom = 0.0f;
    float e[NPTS];
#pragma unroll
    for (int p = 0; p < NPTS; p++) { e[p] = expf(score[p] - mx); denom += e[p]; }
    float inv = 1.0f / denom;

    float4 acc = make_float4(0.f, 0.f, 0.f, 0.f);
#pragma unroll
    for (int p = 0; p < NPTS; p++) {
        float a = e[p] * inv;
        acc.x += a * sk[p][0];
        acc.y += a * sk[p][1];
        acc.z += a * sk[p][2];
        acc.w += a * sk[p][3];
    }
    *reinterpret_cast<float4*>(out + (size_t)m * CC + ch) = acc;
}

// ---------------------------------------------------------------------------
extern "C" void kernel_launch(void* const* d_in, const int* in_sizes, int n_in,
                              void* d_out, int out_size) {
    const float* query = (const float*)d_in[0];
    const float* ref   = (const float*)d_in[1];
    const float* Wq    = (const float*)d_in[2];
    const float* bq    = (const float*)d_in[3];
    const float* Wkv   = (const float*)d_in[4];
    const float* bkv   = (const float*)d_in[5];
    const float* Woff  = (const float*)d_in[6];
    const float* boff  = (const float*)d_in[7];
    const float* Wout  = (const float*)d_in[8];
    const float* bout  = (const float*)d_in[9];
    float* outp = (float*)d_out;

    __nv_bfloat16 *abig, *bq_op, *bk_op, *bo_op, *bf_op;
    float *qb, *kb, *offp, *attnb;
    cudaGetSymbolAddress((void**)&abig,  g_abig);
    cudaGetSymbolAddress((void**)&bq_op, g_bop_q);
    cudaGetSymbolAddress((void**)&bk_op, g_bop_k);
    cudaGetSymbolAddress((void**)&bo_op, g_bop_o);
    cudaGetSymbolAddress((void**)&bf_op, g_bop_f);
    cudaGetSymbolAddress((void**)&qb,    g_q);
    cudaGetSymbolAddress((void**)&kb,    g_k);
    cudaGetSymbolAddress((void**)&offp,  g_offp);
    cudaGetSymbolAddress((void**)&attnb, g_attn);

    cudaFuncSetAttribute(gemm_hmma, cudaFuncAttributeMaxDynamicSharedMemorySize, SMEM_SZ);

    const int mtiles = (MM + 127) / 128;  // 86
    dim3 wblk(32, 8);

    // weight conversions
    conv_w<<<dim3(32, 32), wblk>>>(Wq,  CC,     CC,  bq_op);
    conv_w<<<dim3(32, 32), wblk>>>(Wkv, 2 * CC, CC,  bk_op);
    conv_w<<<dim3(32, 32), wblk>>>(Wout, CC,    CC,  bo_op);
    conv_w<<<dim3(4, 32),  wblk>>>(Woff, NHEADS * NPTS * 2, NHEADS * NPTS * 2, bf_op);

    const int cablk = (int)(((size_t)MM * 128 + 255) / 256);

    // q = query @ Wq + bq ; off = query @ Woff + boff
    conv_act<<<cablk, 256>>>(query, abig);
    gemm_hmma<<<dim3(8, mtiles), 256, SMEM_SZ>>>(abig, bq_op, bq, qb, MM, CC);
    gemm_hmma<<<dim3(1, mtiles), 256, SMEM_SZ>>>(abig, bf_op, boff, offp, MM, 128);

    // k = ref @ Wkv[:, :C] + bkv[:C]
    conv_act<<<cablk, 256>>>(ref, abig);
    gemm_hmma<<<dim3(8, mtiles), 256, SMEM_SZ>>>(abig, bk_op, bkv, kb, MM, CC);

    // sampling + softmax attention
    {
        int warps = MM * NHEADS;
        int blocks = (warps * 32 + 255) / 256;
        sample_attn_kernel<<<blocks, 256>>>(qb, kb, offp, attnb);
    }

    // out = attn @ Wout + bout
    conv_act<<<cablk, 256>>>(attnb, abig);
    gemm_hmma<<<dim3(8, mtiles), 256, SMEM_SZ>>>(abig, bo_op, bout, outp, MM, CC);
}